// round 15
// baseline (speedup 1.0000x reference)
#include <cuda_runtime.h>
#include <cuda_fp16.h>
#include <cstdint>
#include <mma.h>
#include <math.h>

using namespace nvcuda;

// ---------------- problem constants ----------------
#define NTOK 8192          // B*S
#define DDIM 1024
#define HDIM 4096
#define NEXP 8
#define BM 128
#define BN 128
#define BK 32
#define NSTAGE 6           // 3 groups x 2 stages
#define CAP 17408          // 2*NTOK + NEXP*BM
#define NTHREADS 128

// Stage geometry (halves): A[128][40] + B[32][136]
#define A_LD 40
#define B_LD 136
#define A_HALFS (BM * A_LD)                      // 5120
#define STAGE_HALFS (A_HALFS + BK * B_LD)        // 9472
#define SMEM_BYTES (NSTAGE * STAGE_HALFS * 2)    // 113664 (x2 CTA = 227328 <= 228KB)

// ---------------- scratch (device globals; no allocation) ----------------
__device__ int    g_e[NTOK * 2];
__device__ float  g_wt[NTOK * 2];
__device__ int    g_count[NEXP];
__device__ int    g_cursor[NEXP];
__device__ int    g_slot[NTOK * 2];                     // per (token,k): grouped slot index
__device__ int    g_tok[CAP];
__device__ float  g_gwt[CAP];
__device__ __half g_xh[(size_t)NTOK * DDIM];            // fp16 x
__device__ __half g_W1h[(size_t)NEXP * DDIM * HDIM];    // fp16 W1 [E][D][H]
__device__ __half g_W2h[(size_t)NEXP * HDIM * DDIM];    // fp16 W2 [E][H][D]
__device__ __half g_Hh[(size_t)CAP * HDIM];             // fc1 output (grouped, fp16)
__device__ float  g_Y[(size_t)CAP * DDIM];              // weighted fc2 output per slot

// ---------------- helpers ----------------
__device__ __forceinline__ void cp16(void* dst_smem, const void* src_gmem) {
    unsigned int s = (unsigned int)__cvta_generic_to_shared(dst_smem);
    asm volatile("cp.async.cg.shared.global [%0], [%1], 16;\n" :: "r"(s), "l"(src_gmem));
}
__device__ __forceinline__ void cp_commit() {
    asm volatile("cp.async.commit_group;\n" ::: "memory");
}
template <int N>
__device__ __forceinline__ void cp_wait() {
    asm volatile("cp.async.wait_group %0;\n" :: "n"(N) : "memory");
}
__device__ __forceinline__ float gelu_exact(float v) {
    return 0.5f * v * (1.0f + erff(v * 0.70710678118654752f));
}
__device__ __forceinline__ uint2 cvt4(float4 v) {
    __half2 h0 = __floats2half2_rn(v.x, v.y);
    __half2 h1 = __floats2half2_rn(v.z, v.w);
    uint2 u;
    u.x = *(unsigned*)&h0;
    u.y = *(unsigned*)&h1;
    return u;
}
// padded exclusive scan over experts, computed locally (g_count final post-router)
__device__ __forceinline__ int padded_base(int e) {
    int b = 0;
    for (int ee = 0; ee < e; ee++) b += ((g_count[ee] + BM - 1) / BM) * BM;
    return b;
}

// ---------------- small kernels ----------------
// W1 conversion + zero counters (launch #1)
__global__ void k_prep_w1(const float* __restrict__ src) {
    size_t i = (size_t)blockIdx.x * blockDim.x + threadIdx.x;
    if (blockIdx.x == 0 && threadIdx.x < NEXP) {
        g_count[threadIdx.x] = 0;
        g_cursor[threadIdx.x] = 0;
    }
    ((uint2*)g_W1h)[i] = cvt4(((const float4*)src)[i]);
}
__global__ void k_half_w2(const float* __restrict__ src) {
    size_t i = (size_t)blockIdx.x * blockDim.x + threadIdx.x;
    ((uint2*)g_W2h)[i] = cvt4(((const float4*)src)[i]);
}

// router (launch #2) — also converts x to fp16 (it already reads every element)
__global__ void k_router(const float* __restrict__ x, const float* __restrict__ Wr) {
    int warp = (blockIdx.x * blockDim.x + threadIdx.x) >> 5;
    int lane = threadIdx.x & 31;
    if (warp >= NTOK) return;
    const float* xr = x + (size_t)warp * DDIM;
    __half* xh = g_xh + (size_t)warp * DDIM;
    float acc[NEXP];
#pragma unroll
    for (int e = 0; e < NEXP; e++) acc[e] = 0.0f;
    for (int d = lane * 4; d < DDIM; d += 128) {
        float4 xv = *(const float4*)(xr + d);
        *(uint2*)(xh + d) = cvt4(xv);          // fused x -> fp16
#pragma unroll
        for (int e = 0; e < NEXP; e++) {
            float4 wv = *(const float4*)(Wr + e * DDIM + d);
            acc[e] += xv.x * wv.x + xv.y * wv.y + xv.z * wv.z + xv.w * wv.w;
        }
    }
#pragma unroll
    for (int e = 0; e < NEXP; e++) {
#pragma unroll
        for (int off = 16; off > 0; off >>= 1)
            acc[e] += __shfl_xor_sync(0xffffffffu, acc[e], off);
    }
    if (lane == 0) {
        float mx = acc[0];
#pragma unroll
        for (int e = 1; e < NEXP; e++) mx = fmaxf(mx, acc[e]);
        float p[NEXP]; float s = 0.0f;
#pragma unroll
        for (int e = 0; e < NEXP; e++) { p[e] = expf(acc[e] - mx); s += p[e]; }
        int i0 = 0;
#pragma unroll
        for (int e = 1; e < NEXP; e++) if (p[e] > p[i0]) i0 = e;
        int i1 = (i0 == 0) ? 1 : 0;
#pragma unroll
        for (int e = 0; e < NEXP; e++) if (e != i0 && p[e] > p[i1]) i1 = e;
        float inv = 1.0f / s;
        g_e[2 * warp]     = i0;  g_wt[2 * warp]     = p[i0] * inv;
        g_e[2 * warp + 1] = i1;  g_wt[2 * warp + 1] = p[i1] * inv;
        atomicAdd(&g_count[i0], 1);
        atomicAdd(&g_count[i1], 1);
    }
}

// build (launch #3) — computes padded scan locally, no separate k_scan
__global__ void k_build() {
    int t = blockIdx.x * blockDim.x + threadIdx.x;
    if (t >= NTOK) return;
    int base[NEXP];
    {
        int b = 0;
#pragma unroll
        for (int e = 0; e < NEXP; e++) {
            base[e] = b;
            b += ((g_count[e] + BM - 1) / BM) * BM;
        }
    }
#pragma unroll
    for (int s = 0; s < 2; s++) {
        int e = g_e[2 * t + s];
        int pos = atomicAdd(&g_cursor[e], 1);
        int idx = base[e] + pos;
        g_tok[idx] = t;
        g_gwt[idx] = g_wt[2 * t + s];
        g_slot[2 * t + s] = idx;
    }
}

// final combine: out[t] = Y[slot0(t)] + Y[slot1(t)]
__global__ void k_combine(float* __restrict__ out) {
    int i = blockIdx.x * blockDim.x + threadIdx.x;    // float4 index over NTOK*DDIM/4
    int t = i >> 8;                                   // DDIM/4 = 256
    int c = i & 255;
    int s0 = g_slot[2 * t], s1 = g_slot[2 * t + 1];
    float4 a = ((const float4*)g_Y)[(size_t)s0 * 256 + c];
    float4 b = ((const float4*)g_Y)[(size_t)s1 * 256 + c];
    float4 v;
    v.x = a.x + b.x; v.y = a.y + b.y; v.z = a.z + b.z; v.w = a.w + b.w;
    ((float4*)out)[i] = v;
}

// ---------------- pipelined tile loaders (fp16, 16B = 8 halves; 128 thr) ------
__device__ __forceinline__ void load_A_gather(__half* As, const __half* __restrict__ x,
                                              const int* s_tok, int k0, int tid) {
#pragma unroll
    for (int i = 0; i < 4; i++) {
        int idx = tid + i * NTHREADS;
        int r = idx >> 2, c8 = idx & 3;
        cp16(As + r * A_LD + c8 * 8, x + (size_t)s_tok[r] * DDIM + k0 + c8 * 8);
    }
}
__device__ __forceinline__ void load_A_rows(__half* As, const __half* __restrict__ src,
                                            int ld, int k0, int tid) {
#pragma unroll
    for (int i = 0; i < 4; i++) {
        int idx = tid + i * NTHREADS;
        int r = idx >> 2, c8 = idx & 3;
        cp16(As + r * A_LD + c8 * 8, src + (size_t)r * ld + k0 + c8 * 8);
    }
}
__device__ __forceinline__ void load_B(__half* Bs, const __half* __restrict__ W,
                                       int ldw, int k0, int n0, int tid) {
#pragma unroll
    for (int i = 0; i < 4; i++) {
        int idx = tid + i * NTHREADS;
        int r = idx >> 4, c8 = idx & 15;
        cp16(Bs + r * B_LD + c8 * 8, W + (size_t)(k0 + r) * ldw + n0 + c8 * 8);
    }
}

// warp-tile compute on one stage: 64x64 per warp (2x2 warp grid), HMMA-dense
__device__ __forceinline__ void compute_stage(
    const __half* As, const __half* Bs, int wm, int wn,
    wmma::fragment<wmma::accumulator, 16, 16, 16, float> (&acc)[4][4]) {
#pragma unroll
    for (int ks = 0; ks < 2; ks++) {
        wmma::fragment<wmma::matrix_a, 16, 16, 16, __half, wmma::row_major> af[4];
        wmma::fragment<wmma::matrix_b, 16, 16, 16, __half, wmma::row_major> bf[4];
#pragma unroll
        for (int m = 0; m < 4; m++)
            wmma::load_matrix_sync(af[m], As + (wm * 64 + m * 16) * A_LD + ks * 16, A_LD);
#pragma unroll
        for (int n = 0; n < 4; n++)
            wmma::load_matrix_sync(bf[n], Bs + ks * 16 * B_LD + wn * 64 + n * 16, B_LD);
#pragma unroll
        for (int m = 0; m < 4; m++)
#pragma unroll
            for (int n = 0; n < 4; n++)
                wmma::mma_sync(acc[m][n], af[m], bf[n], acc[m][n]);
    }
}

// ---------------- GEMM1: H = gelu(gather(xh) @ W1h[e] + b1[e]) ----------------
__global__ __launch_bounds__(NTHREADS, 2) void k_gemm1(const float* __restrict__ b1) {
    extern __shared__ __align__(128) __half smem[];
    const int e = blockIdx.z;
    const int cnt = g_count[e];
    const int m0 = blockIdx.y * BM;
    if (m0 >= cnt) return;
    const int n0 = blockIdx.x * BN;
    const int rowbase = padded_base(e) + m0;
    const __half* W1e = g_W1h + (size_t)e * DDIM * HDIM;
    const int tid = threadIdx.x;
    const int wid = tid >> 5;
    const int wm = wid & 1, wn = wid >> 1;   // 2x2 warp grid

    __shared__ int s_tok[BM];
    if (tid < BM) {
        int r = m0 + tid;
        s_tok[tid] = (r < cnt) ? g_tok[rowbase - m0 + r] : g_tok[rowbase - m0];
    }
    __syncthreads();

    wmma::fragment<wmma::accumulator, 16, 16, 16, float> acc[4][4];
#pragma unroll
    for (int m = 0; m < 4; m++)
#pragma unroll
        for (int n = 0; n < 4; n++) wmma::fill_fragment(acc[m][n], 0.0f);

    // prologue: groups 0,1 (stages 0..3)
#pragma unroll
    for (int g = 0; g < 2; g++) {
#pragma unroll
        for (int st = 0; st < 2; st++) {
            __half* s = smem + (2 * g + st) * STAGE_HALFS;
            load_A_gather(s, g_xh, s_tok, (2 * g + st) * BK, tid);
            load_B(s + A_HALFS, W1e, HDIM, (2 * g + st) * BK, n0, tid);
        }
        cp_commit();
    }

    const int NIT = DDIM / (2 * BK);  // 16
    for (int j = 0; j < NIT; j++) {
        cp_wait<1>();
        __syncthreads();
        int pf = j + 2;
        if (pf < NIT) {
#pragma unroll
            for (int st = 0; st < 2; st++) {
                __half* s = smem + ((pf % 3) * 2 + st) * STAGE_HALFS;
                load_A_gather(s, g_xh, s_tok, (2 * pf + st) * BK, tid);
                load_B(s + A_HALFS, W1e, HDIM, (2 * pf + st) * BK, n0, tid);
            }
        }
        cp_commit();                           // unconditional: keeps group accounting exact
#pragma unroll
        for (int st = 0; st < 2; st++) {
            __half* cur = smem + ((j % 3) * 2 + st) * STAGE_HALFS;
            compute_stage(cur, cur + A_HALFS, wm, wn, acc);
        }
    }
    cp_wait<0>();

    // epilogue: whole 128x128 fp32 tile staged (69.6KB <= 113.6KB smem)
    float* fsm = (float*)smem;
    const float* b1e = b1 + e * HDIM;
    __syncthreads();
#pragma unroll
    for (int m = 0; m < 4; m++)
#pragma unroll
        for (int n = 0; n < 4; n++)
            wmma::store_matrix_sync(fsm + (wm * 64 + m * 16) * B_LD + wn * 64 + n * 16,
                                    acc[m][n], B_LD, wmma::mem_row_major);
    __syncthreads();
#pragma unroll
    for (int i = 0; i < 32; i++) {
        int idx = tid + i * NTHREADS;           // 4096 chunks of 4 = 128 rows x 32
        int r = idx >> 5, c4 = (idx & 31) * 4;
        float4 v;
        v.x = gelu_exact(fsm[r * B_LD + c4 + 0] + b1e[n0 + c4 + 0]);
        v.y = gelu_exact(fsm[r * B_LD + c4 + 1] + b1e[n0 + c4 + 1]);
        v.z = gelu_exact(fsm[r * B_LD + c4 + 2] + b1e[n0 + c4 + 2]);
        v.w = gelu_exact(fsm[r * B_LD + c4 + 3] + b1e[n0 + c4 + 3]);
        *(uint2*)(g_Hh + (size_t)(rowbase + r) * HDIM + n0 + c4) = cvt4(v);
    }
}

// ---------------- GEMM2: Y[slot] = wt * (H @ W2h[e] + b2[e]) — no atomics ------
__global__ __launch_bounds__(NTHREADS, 2) void k_gemm2(const float* __restrict__ b2) {
    extern __shared__ __align__(128) __half smem[];
    const int e = blockIdx.z;
    const int cnt = g_count[e];
    const int m0 = blockIdx.y * BM;
    if (m0 >= cnt) return;
    const int n0 = blockIdx.x * BN;
    const int rowbase = padded_base(e) + m0;
    const __half* W2e = g_W2h + (size_t)e * HDIM * DDIM;
    const int tid = threadIdx.x;
    const int wid = tid >> 5;
    const int wm = wid & 1, wn = wid >> 1;

    __shared__ float s_wt[BM];
    if (tid < BM) {
        s_wt[tid] = g_gwt[rowbase + tid];
    }
    __syncthreads();

    wmma::fragment<wmma::accumulator, 16, 16, 16, float> acc[4][4];
#pragma unroll
    for (int m = 0; m < 4; m++)
#pragma unroll
        for (int n = 0; n < 4; n++) wmma::fill_fragment(acc[m][n], 0.0f);

    const __half* Hrows = g_Hh + (size_t)rowbase * HDIM;

#pragma unroll
    for (int g = 0; g < 2; g++) {
#pragma unroll
        for (int st = 0; st < 2; st++) {
            __half* s = smem + (2 * g + st) * STAGE_HALFS;
            load_A_rows(s, Hrows, HDIM, (2 * g + st) * BK, tid);
            load_B(s + A_HALFS, W2e, DDIM, (2 * g + st) * BK, n0, tid);
        }
        cp_commit();
    }

    const int NIT = HDIM / (2 * BK);  // 64
    for (int j = 0; j < NIT; j++) {
        cp_wait<1>();
        __syncthreads();
        int pf = j + 2;
        if (pf < NIT) {
#pragma unroll
            for (int st = 0; st < 2; st++) {
                __half* s = smem + ((pf % 3) * 2 + st) * STAGE_HALFS;
                load_A_rows(s, Hrows, HDIM, (2 * pf + st) * BK, tid);
                load_B(s + A_HALFS, W2e, DDIM, (2 * pf + st) * BK, n0, tid);
            }
        }
        cp_commit();
#pragma unroll
        for (int st = 0; st < 2; st++) {
            __half* cur = smem + ((j % 3) * 2 + st) * STAGE_HALFS;
            compute_stage(cur, cur + A_HALFS, wm, wn, acc);
        }
    }
    cp_wait<0>();

    float* fsm = (float*)smem;
    const float* b2e = b2 + e * DDIM;
    __syncthreads();
#pragma unroll
    for (int m = 0; m < 4; m++)
#pragma unroll
        for (int n = 0; n < 4; n++)
            wmma::store_matrix_sync(fsm + (wm * 64 + m * 16) * B_LD + wn * 64 + n * 16,
                                    acc[m][n], B_LD, wmma::mem_row_major);
    __syncthreads();
#pragma unroll
    for (int i = 0; i < 32; i++) {
        int idx = tid + i * NTHREADS;           // 4096 chunks of 4 = 128 rows x 32
        int r = idx >> 5, c4 = (idx & 31) * 4;
        float wt = s_wt[r];
        float4 v;
        v.x = wt * (fsm[r * B_LD + c4 + 0] + b2e[n0 + c4 + 0]);
        v.y = wt * (fsm[r * B_LD + c4 + 1] + b2e[n0 + c4 + 1]);
        v.z = wt * (fsm[r * B_LD + c4 + 2] + b2e[n0 + c4 + 2]);
        v.w = wt * (fsm[r * B_LD + c4 + 3] + b2e[n0 + c4 + 3]);
        *(float4*)(g_Y + (size_t)(rowbase + r) * DDIM + n0 + c4) = v;
    }
}

// ---------------- launch ----------------
extern "C" void kernel_launch(void* const* d_in, const int* in_sizes, int n_in,
                              void* d_out, int out_size) {
    const float* x  = (const float*)d_in[0];
    const float* Wr = (const float*)d_in[1];
    const float* W1 = (const float*)d_in[2];
    const float* b1 = (const float*)d_in[3];
    const float* W2 = (const float*)d_in[4];
    const float* b2 = (const float*)d_in[5];
    float* out = (float*)d_out;

    cudaFuncSetAttribute(k_gemm1, cudaFuncAttributeMaxDynamicSharedMemorySize, SMEM_BYTES);
    cudaFuncSetAttribute(k_gemm2, cudaFuncAttributeMaxDynamicSharedMemorySize, SMEM_BYTES);

    // Launch order chosen so k_gemm1 is the 4th launch (ncu capture slot).
    k_prep_w1<<<(int)(((size_t)NEXP * DDIM * HDIM / 4) / 256), 256>>>(W1);   // #1: W1->fp16 + zero counters
    k_router<<<NTOK / 8, 256>>>(x, Wr);                                      // #2: route + x->fp16
    k_build<<<NTOK / 256, 256>>>();                                          // #3: grouped lists (local scan)
    k_gemm1<<<dim3(HDIM / BN, 64, NEXP), NTHREADS, SMEM_BYTES>>>(b1);        // #4: PROFILED
    k_half_w2<<<(int)(((size_t)NEXP * HDIM * DDIM / 4) / 256), 256>>>(W2);   // #5
    k_gemm2<<<dim3(DDIM / BN, 64, NEXP), NTHREADS, SMEM_BYTES>>>(b2);        // #6
    k_combine<<<(NTOK * DDIM / 4) / 256, 256>>>(out);                        // #7
}

// round 17
// speedup vs baseline: 1.0893x; 1.0893x over previous
#include <cuda_runtime.h>
#include <cuda_fp16.h>
#include <cstdint>
#include <mma.h>
#include <math.h>

using namespace nvcuda;

// ---------------- problem constants ----------------
#define NTOK 8192          // B*S
#define DDIM 1024
#define HDIM 4096
#define NEXP 8
#define BM 128
#define BN 128
#define BK 32
#define NSTAGE 4
#define CAP 17408          // 2*NTOK + NEXP*BM
#define NTHREADS 128

// Stage geometry (halves): A[128][40] + B[32][136]
#define A_LD 40
#define B_LD 136
#define A_HALFS (BM * A_LD)                      // 5120
#define STAGE_HALFS (A_HALFS + BK * B_LD)        // 9472
#define SMEM_BYTES (NSTAGE * STAGE_HALFS * 2)    // 75776 (x3 CTA = 227328 <= 228KB)

// ---------------- scratch (device globals; no allocation) ----------------
__device__ int    g_e[NTOK * 2];
__device__ float  g_wt[NTOK * 2];
__device__ int    g_count[NEXP];
__device__ int    g_cursor[NEXP];
__device__ int    g_slot[NTOK * 2];                     // per (token,k): grouped slot index
__device__ int    g_tok[CAP];
__device__ float  g_gwt[CAP];
__device__ __half g_xh[(size_t)NTOK * DDIM];            // fp16 x
__device__ __half g_W1h[(size_t)NEXP * DDIM * HDIM];    // fp16 W1 [E][D][H]
__device__ __half g_W2h[(size_t)NEXP * HDIM * DDIM];    // fp16 W2 [E][H][D]
__device__ __half g_Hh[(size_t)CAP * HDIM];             // fc1 output (grouped, fp16)
__device__ float  g_Y[(size_t)CAP * DDIM];              // weighted fc2 output per slot

// ---------------- helpers ----------------
__device__ __forceinline__ void cp16(void* dst_smem, const void* src_gmem) {
    unsigned int s = (unsigned int)__cvta_generic_to_shared(dst_smem);
    asm volatile("cp.async.cg.shared.global [%0], [%1], 16;\n" :: "r"(s), "l"(src_gmem));
}
__device__ __forceinline__ void cp_commit() {
    asm volatile("cp.async.commit_group;\n" ::: "memory");
}
template <int N>
__device__ __forceinline__ void cp_wait() {
    asm volatile("cp.async.wait_group %0;\n" :: "n"(N) : "memory");
}
__device__ __forceinline__ float gelu_exact(float v) {
    return 0.5f * v * (1.0f + erff(v * 0.70710678118654752f));
}
__device__ __forceinline__ uint2 cvt4(float4 v) {
    __half2 h0 = __floats2half2_rn(v.x, v.y);
    __half2 h1 = __floats2half2_rn(v.z, v.w);
    uint2 u;
    u.x = *(unsigned*)&h0;
    u.y = *(unsigned*)&h1;
    return u;
}
// padded exclusive scan over experts, computed locally (g_count final post-router)
__device__ __forceinline__ int padded_base(int e) {
    int b = 0;
    for (int ee = 0; ee < e; ee++) b += ((g_count[ee] + BM - 1) / BM) * BM;
    return b;
}

// ---------------- small kernels ----------------
// W1 conversion + zero counters (launch #1)
__global__ void k_prep_w1(const float* __restrict__ src) {
    size_t i = (size_t)blockIdx.x * blockDim.x + threadIdx.x;
    if (blockIdx.x == 0 && threadIdx.x < NEXP) {
        g_count[threadIdx.x] = 0;
        g_cursor[threadIdx.x] = 0;
    }
    ((uint2*)g_W1h)[i] = cvt4(((const float4*)src)[i]);
}
__global__ void k_half_w2(const float* __restrict__ src) {
    size_t i = (size_t)blockIdx.x * blockDim.x + threadIdx.x;
    ((uint2*)g_W2h)[i] = cvt4(((const float4*)src)[i]);
}

// router (launch #2) — also converts x to fp16 (it already reads every element)
__global__ void k_router(const float* __restrict__ x, const float* __restrict__ Wr) {
    int warp = (blockIdx.x * blockDim.x + threadIdx.x) >> 5;
    int lane = threadIdx.x & 31;
    if (warp >= NTOK) return;
    const float* xr = x + (size_t)warp * DDIM;
    __half* xh = g_xh + (size_t)warp * DDIM;
    float acc[NEXP];
#pragma unroll
    for (int e = 0; e < NEXP; e++) acc[e] = 0.0f;
    for (int d = lane * 4; d < DDIM; d += 128) {
        float4 xv = *(const float4*)(xr + d);
        *(uint2*)(xh + d) = cvt4(xv);          // fused x -> fp16
#pragma unroll
        for (int e = 0; e < NEXP; e++) {
            float4 wv = *(const float4*)(Wr + e * DDIM + d);
            acc[e] += xv.x * wv.x + xv.y * wv.y + xv.z * wv.z + xv.w * wv.w;
        }
    }
#pragma unroll
    for (int e = 0; e < NEXP; e++) {
#pragma unroll
        for (int off = 16; off > 0; off >>= 1)
            acc[e] += __shfl_xor_sync(0xffffffffu, acc[e], off);
    }
    if (lane == 0) {
        float mx = acc[0];
#pragma unroll
        for (int e = 1; e < NEXP; e++) mx = fmaxf(mx, acc[e]);
        float p[NEXP]; float s = 0.0f;
#pragma unroll
        for (int e = 0; e < NEXP; e++) { p[e] = expf(acc[e] - mx); s += p[e]; }
        int i0 = 0;
#pragma unroll
        for (int e = 1; e < NEXP; e++) if (p[e] > p[i0]) i0 = e;
        int i1 = (i0 == 0) ? 1 : 0;
#pragma unroll
        for (int e = 0; e < NEXP; e++) if (e != i0 && p[e] > p[i1]) i1 = e;
        float inv = 1.0f / s;
        g_e[2 * warp]     = i0;  g_wt[2 * warp]     = p[i0] * inv;
        g_e[2 * warp + 1] = i1;  g_wt[2 * warp + 1] = p[i1] * inv;
        atomicAdd(&g_count[i0], 1);
        atomicAdd(&g_count[i1], 1);
    }
}

// build (launch #3) — computes padded scan locally, no separate k_scan
__global__ void k_build() {
    int t = blockIdx.x * blockDim.x + threadIdx.x;
    if (t >= NTOK) return;
    int base[NEXP];
    {
        int b = 0;
#pragma unroll
        for (int e = 0; e < NEXP; e++) {
            base[e] = b;
            b += ((g_count[e] + BM - 1) / BM) * BM;
        }
    }
#pragma unroll
    for (int s = 0; s < 2; s++) {
        int e = g_e[2 * t + s];
        int pos = atomicAdd(&g_cursor[e], 1);
        int idx = base[e] + pos;
        g_tok[idx] = t;
        g_gwt[idx] = g_wt[2 * t + s];
        g_slot[2 * t + s] = idx;
    }
}

// final combine: out[t] = Y[slot0(t)] + Y[slot1(t)]
__global__ void k_combine(float* __restrict__ out) {
    int i = blockIdx.x * blockDim.x + threadIdx.x;    // float4 index over NTOK*DDIM/4
    int t = i >> 8;                                   // DDIM/4 = 256
    int c = i & 255;
    int s0 = g_slot[2 * t], s1 = g_slot[2 * t + 1];
    float4 a = ((const float4*)g_Y)[(size_t)s0 * 256 + c];
    float4 b = ((const float4*)g_Y)[(size_t)s1 * 256 + c];
    float4 v;
    v.x = a.x + b.x; v.y = a.y + b.y; v.z = a.z + b.z; v.w = a.w + b.w;
    ((float4*)out)[i] = v;
}

// ---------------- pipelined tile loaders (fp16, 16B = 8 halves; 128 thr) ------
__device__ __forceinline__ void load_A_gather(__half* As, const __half* __restrict__ x,
                                              const int* s_tok, int k0, int tid) {
#pragma unroll
    for (int i = 0; i < 4; i++) {
        int idx = tid + i * NTHREADS;
        int r = idx >> 2, c8 = idx & 3;
        cp16(As + r * A_LD + c8 * 8, x + (size_t)s_tok[r] * DDIM + k0 + c8 * 8);
    }
}
__device__ __forceinline__ void load_A_rows(__half* As, const __half* __restrict__ src,
                                            int ld, int k0, int tid) {
#pragma unroll
    for (int i = 0; i < 4; i++) {
        int idx = tid + i * NTHREADS;
        int r = idx >> 2, c8 = idx & 3;
        cp16(As + r * A_LD + c8 * 8, src + (size_t)r * ld + k0 + c8 * 8);
    }
}
__device__ __forceinline__ void load_B(__half* Bs, const __half* __restrict__ W,
                                       int ldw, int k0, int n0, int tid) {
#pragma unroll
    for (int i = 0; i < 4; i++) {
        int idx = tid + i * NTHREADS;
        int r = idx >> 4, c8 = idx & 15;
        cp16(Bs + r * B_LD + c8 * 8, W + (size_t)(k0 + r) * ldw + n0 + c8 * 8);
    }
}

// warp-tile compute on one stage: 64x64 per warp (2x2 warp grid), HMMA-dense
__device__ __forceinline__ void compute_stage(
    const __half* As, const __half* Bs, int wm, int wn,
    wmma::fragment<wmma::accumulator, 16, 16, 16, float> (&acc)[4][4]) {
#pragma unroll
    for (int ks = 0; ks < 2; ks++) {
        wmma::fragment<wmma::matrix_a, 16, 16, 16, __half, wmma::row_major> af[4];
        wmma::fragment<wmma::matrix_b, 16, 16, 16, __half, wmma::row_major> bf[4];
#pragma unroll
        for (int m = 0; m < 4; m++)
            wmma::load_matrix_sync(af[m], As + (wm * 64 + m * 16) * A_LD + ks * 16, A_LD);
#pragma unroll
        for (int n = 0; n < 4; n++)
            wmma::load_matrix_sync(bf[n], Bs + ks * 16 * B_LD + wn * 64 + n * 16, B_LD);
#pragma unroll
        for (int m = 0; m < 4; m++)
#pragma unroll
            for (int n = 0; n < 4; n++)
                wmma::mma_sync(acc[m][n], af[m], bf[n], acc[m][n]);
    }
}

// ---------------- GEMM1: H = gelu(gather(xh) @ W1h[e] + b1[e]) ----------------
__global__ __launch_bounds__(NTHREADS, 3) void k_gemm1(const float* __restrict__ b1) {
    extern __shared__ __align__(128) __half smem[];
    const int e = blockIdx.z;
    const int cnt = g_count[e];
    const int m0 = blockIdx.y * BM;
    if (m0 >= cnt) return;
    const int n0 = blockIdx.x * BN;
    const int rowbase = padded_base(e) + m0;
    const __half* W1e = g_W1h + (size_t)e * DDIM * HDIM;
    const int tid = threadIdx.x;
    const int wid = tid >> 5;
    const int wm = wid & 1, wn = wid >> 1;   // 2x2 warp grid

    __shared__ int s_tok[BM];
    if (tid < BM) {
        int r = m0 + tid;
        s_tok[tid] = (r < cnt) ? g_tok[rowbase - m0 + r] : g_tok[rowbase - m0];
    }
    __syncthreads();

    wmma::fragment<wmma::accumulator, 16, 16, 16, float> acc[4][4];
#pragma unroll
    for (int m = 0; m < 4; m++)
#pragma unroll
        for (int n = 0; n < 4; n++) wmma::fill_fragment(acc[m][n], 0.0f);

#pragma unroll
    for (int s = 0; s < NSTAGE - 1; s++) {
        __half* st = smem + s * STAGE_HALFS;
        load_A_gather(st, g_xh, s_tok, s * BK, tid);
        load_B(st + A_HALFS, W1e, HDIM, s * BK, n0, tid);
        cp_commit();
    }

    const int KT = DDIM / BK;  // 32
    for (int kt = 0; kt < KT; kt++) {
        cp_wait<NSTAGE - 2>();
        __syncthreads();
        int pf = kt + NSTAGE - 1;
        if (pf < KT) {
            __half* st = smem + (pf % NSTAGE) * STAGE_HALFS;
            load_A_gather(st, g_xh, s_tok, pf * BK, tid);
            load_B(st + A_HALFS, W1e, HDIM, pf * BK, n0, tid);
        }
        cp_commit();
        __half* cur = smem + (kt % NSTAGE) * STAGE_HALFS;
        compute_stage(cur, cur + A_HALFS, wm, wn, acc);
    }
    cp_wait<0>();

    // epilogue: whole 128x128 fp32 tile staged (69.6KB <= 75.8KB smem)
    float* fsm = (float*)smem;
    const float* b1e = b1 + e * HDIM;
    __syncthreads();
#pragma unroll
    for (int m = 0; m < 4; m++)
#pragma unroll
        for (int n = 0; n < 4; n++)
            wmma::store_matrix_sync(fsm + (wm * 64 + m * 16) * B_LD + wn * 64 + n * 16,
                                    acc[m][n], B_LD, wmma::mem_row_major);
    __syncthreads();
#pragma unroll
    for (int i = 0; i < 32; i++) {
        int idx = tid + i * NTHREADS;           // 4096 chunks of 4 = 128 rows x 32
        int r = idx >> 5, c4 = (idx & 31) * 4;
        float4 v;
        v.x = gelu_exact(fsm[r * B_LD + c4 + 0] + b1e[n0 + c4 + 0]);
        v.y = gelu_exact(fsm[r * B_LD + c4 + 1] + b1e[n0 + c4 + 1]);
        v.z = gelu_exact(fsm[r * B_LD + c4 + 2] + b1e[n0 + c4 + 2]);
        v.w = gelu_exact(fsm[r * B_LD + c4 + 3] + b1e[n0 + c4 + 3]);
        *(uint2*)(g_Hh + (size_t)(rowbase + r) * HDIM + n0 + c4) = cvt4(v);
    }
}

// ---------------- GEMM2: Y[slot] = wt * (H @ W2h[e] + b2[e]) — no atomics ------
__global__ __launch_bounds__(NTHREADS, 3) void k_gemm2(const float* __restrict__ b2) {
    extern __shared__ __align__(128) __half smem[];
    const int e = blockIdx.z;
    const int cnt = g_count[e];
    const int m0 = blockIdx.y * BM;
    if (m0 >= cnt) return;
    const int n0 = blockIdx.x * BN;
    const int rowbase = padded_base(e) + m0;
    const __half* W2e = g_W2h + (size_t)e * HDIM * DDIM;
    const int tid = threadIdx.x;
    const int wid = tid >> 5;
    const int wm = wid & 1, wn = wid >> 1;

    __shared__ float s_wt[BM];
    if (tid < BM) {
        s_wt[tid] = g_gwt[rowbase + tid];
    }
    __syncthreads();

    wmma::fragment<wmma::accumulator, 16, 16, 16, float> acc[4][4];
#pragma unroll
    for (int m = 0; m < 4; m++)
#pragma unroll
        for (int n = 0; n < 4; n++) wmma::fill_fragment(acc[m][n], 0.0f);

    const __half* Hrows = g_Hh + (size_t)rowbase * HDIM;

#pragma unroll
    for (int s = 0; s < NSTAGE - 1; s++) {
        __half* st = smem + s * STAGE_HALFS;
        load_A_rows(st, Hrows, HDIM, s * BK, tid);
        load_B(st + A_HALFS, W2e, DDIM, s * BK, n0, tid);
        cp_commit();
    }

    const int KT = HDIM / BK;  // 128
    for (int kt = 0; kt < KT; kt++) {
        cp_wait<NSTAGE - 2>();
        __syncthreads();
        int pf = kt + NSTAGE - 1;
        if (pf < KT) {
            __half* st = smem + (pf % NSTAGE) * STAGE_HALFS;
            load_A_rows(st, Hrows, HDIM, pf * BK, tid);
            load_B(st + A_HALFS, W2e, DDIM, pf * BK, n0, tid);
        }
        cp_commit();
        __half* cur = smem + (kt % NSTAGE) * STAGE_HALFS;
        compute_stage(cur, cur + A_HALFS, wm, wn, acc);
    }
    cp_wait<0>();

    float* fsm = (float*)smem;
    const float* b2e = b2 + e * DDIM;
    __syncthreads();
#pragma unroll
    for (int m = 0; m < 4; m++)
#pragma unroll
        for (int n = 0; n < 4; n++)
            wmma::store_matrix_sync(fsm + (wm * 64 + m * 16) * B_LD + wn * 64 + n * 16,
                                    acc[m][n], B_LD, wmma::mem_row_major);
    __syncthreads();
#pragma unroll
    for (int i = 0; i < 32; i++) {
        int idx = tid + i * NTHREADS;           // 4096 chunks of 4 = 128 rows x 32
        int r = idx >> 5, c4 = (idx & 31) * 4;
        float wt = s_wt[r];
        float4 v;
        v.x = wt * (fsm[r * B_LD + c4 + 0] + b2e[n0 + c4 + 0]);
        v.y = wt * (fsm[r * B_LD + c4 + 1] + b2e[n0 + c4 + 1]);
        v.z = wt * (fsm[r * B_LD + c4 + 2] + b2e[n0 + c4 + 2]);
        v.w = wt * (fsm[r * B_LD + c4 + 3] + b2e[n0 + c4 + 3]);
        *(float4*)(g_Y + (size_t)(rowbase + r) * DDIM + n0 + c4) = v;
    }
}

// ---------------- launch ----------------
extern "C" void kernel_launch(void* const* d_in, const int* in_sizes, int n_in,
                              void* d_out, int out_size) {
    const float* x  = (const float*)d_in[0];
    const float* Wr = (const float*)d_in[1];
    const float* W1 = (const float*)d_in[2];
    const float* b1 = (const float*)d_in[3];
    const float* W2 = (const float*)d_in[4];
    const float* b2 = (const float*)d_in[5];
    float* out = (float*)d_out;

    cudaFuncSetAttribute(k_gemm1, cudaFuncAttributeMaxDynamicSharedMemorySize, SMEM_BYTES);
    cudaFuncSetAttribute(k_gemm2, cudaFuncAttributeMaxDynamicSharedMemorySize, SMEM_BYTES);

    // Launch order chosen so k_gemm1 is the 4th launch (ncu capture slot).
    k_prep_w1<<<(int)(((size_t)NEXP * DDIM * HDIM / 4) / 256), 256>>>(W1);   // #1: W1->fp16 + zero counters
    k_router<<<NTOK / 8, 256>>>(x, Wr);                                      // #2: route + x->fp16
    k_build<<<NTOK / 256, 256>>>();                                          // #3: grouped lists (local scan)
    k_gemm1<<<dim3(HDIM / BN, 64, NEXP), NTHREADS, SMEM_BYTES>>>(b1);        // #4: PROFILED
    k_half_w2<<<(int)(((size_t)NEXP * HDIM * DDIM / 4) / 256), 256>>>(W2);   // #5
    k_gemm2<<<dim3(DDIM / BN, 64, NEXP), NTHREADS, SMEM_BYTES>>>(b2);        // #6
    k_combine<<<(NTOK * DDIM / 4) / 256, 256>>>(out);                        // #7
}